// round 4
// baseline (speedup 1.0000x reference)
#include <cuda_runtime.h>

// LSTM_40948218200110: B=4096, T=1024, I=8, H=4 (PyTorch gate order) + FC[H->1].
// R4: 4 threads per batch element (1 per hidden unit k), TWO independent batch
// chains per thread (cross-chain ILP fills the serial-chain stalls), and
// f32x2 packed FMAs for all dot products (x pairs come packed for free from
// 16B loads). sigmoid 0.5-prescale folded into i/f/o weights.

#define T_STEPS 1024
#define I_DIM   8

typedef unsigned long long ull;

__device__ __forceinline__ float tanh_fast(float x) {
    float y;
    asm("tanh.approx.f32 %0, %1;" : "=f"(y) : "f"(x));
    return y;
}
__device__ __forceinline__ ull ffma2(ull a, ull b, ull c) {
    ull d;
    asm("fma.rn.f32x2 %0, %1, %2, %3;" : "=l"(d) : "l"(a), "l"(b), "l"(c));
    return d;
}
__device__ __forceinline__ ull pack2(float lo, float hi) {
    ull d;
    asm("mov.b64 %0, {%1, %2};" : "=l"(d) : "f"(lo), "f"(hi));
    return d;
}
__device__ __forceinline__ void unpack2(ull v, float& lo, float& hi) {
    asm("mov.b64 {%0, %1}, %2;" : "=f"(lo), "=f"(hi) : "l"(v));
}

struct Chain { float hs, hx1, hx2, hx3, c; };

__global__ __launch_bounds__(64, 1) void lstm_kernel(
    const float* __restrict__ x,     // [B, T, I]
    const float* __restrict__ Wih,   // [16, 8]
    const float* __restrict__ Whh,   // [16, 4]
    const float* __restrict__ bih,   // [16]
    const float* __restrict__ bhh,   // [16]
    const float* __restrict__ fcw,   // [1, 4]
    const float* __restrict__ fcb,   // [1]
    float* __restrict__ out,         // [B, 1]
    int B)
{
    const int tid = blockIdx.x * 64 + threadIdx.x;
    const int grp = tid >> 2;          // chain-pair index
    const int k   = tid & 3;           // hidden unit owned by this thread
    const int nPairs = (B + 1) >> 1;
    if (grp >= nPairs) return;
    const int b0 = 2 * grp;
    const int b1 = (2 * grp + 1 < B) ? (2 * grp + 1) : b0;

    // ---- Packed weights. Gate r in {0:i, 1:f, 2:g, 3:o}; row = 4r + k.
    // i/f/o pre-scaled by 0.5 so sigmoid(z) = 0.5*tanh(z') + 0.5 (fold into fma).
    ull wx[4][4];   // x weights: pairs (w_{2j}, w_{2j+1})
    ull wh[4][2];   // recurrent: (u[k^0],u[k^1]), (u[k^2],u[k^3]) — shfl-permuted
    ull binit[4];   // accumulator init: (bias, 0)
#pragma unroll
    for (int r = 0; r < 4; r++) {
        const int row = 4 * r + k;
        const float s = (r == 2) ? 1.0f : 0.5f;
#pragma unroll
        for (int j = 0; j < 4; j++)
            wx[r][j] = pack2(s * Wih[row * I_DIM + 2 * j], s * Wih[row * I_DIM + 2 * j + 1]);
        wh[r][0] = pack2(s * Whh[row * 4 + (k ^ 0)], s * Whh[row * 4 + (k ^ 1)]);
        wh[r][1] = pack2(s * Whh[row * 4 + (k ^ 2)], s * Whh[row * 4 + (k ^ 3)]);
        binit[r] = pack2(s * (bih[row] + bhh[row]), 0.0f);
    }

    const ulonglong2* xA = reinterpret_cast<const ulonglong2*>(x + (size_t)b0 * T_STEPS * I_DIM);
    const ulonglong2* xB = reinterpret_cast<const ulonglong2*>(x + (size_t)b1 * T_STEPS * I_DIM);

    Chain cA = {0.f, 0.f, 0.f, 0.f, 0.f};
    Chain cB = {0.f, 0.f, 0.f, 0.f, 0.f};

    // One LSTM step for one chain. xa = (x0,x1|x2,x3), xb = (x4,x5|x6,x7).
    auto STEP = [&](Chain& ch, ulonglong2 xa, ulonglong2 xb) {
        const ull h01 = pack2(ch.hs,  ch.hx1);
        const ull h23 = pack2(ch.hx2, ch.hx3);
        float gate[4];
#pragma unroll
        for (int r = 0; r < 4; r++) {
            ull acc = ffma2(wx[r][0], xa.x, binit[r]);
            acc = ffma2(wx[r][1], xa.y, acc);
            acc = ffma2(wx[r][2], xb.x, acc);
            acc = ffma2(wx[r][3], xb.y, acc);
            acc = ffma2(wh[r][0], h01, acc);     // recurrent (critical path)
            acc = ffma2(wh[r][1], h23, acc);
            float lo, hi; unpack2(acc, lo, hi);
            gate[r] = lo + hi;
        }
        const float is = fmaf(tanh_fast(gate[0]), 0.5f, 0.5f);
        const float fs = fmaf(tanh_fast(gate[1]), 0.5f, 0.5f);
        const float gt = tanh_fast(gate[2]);
        const float os = fmaf(tanh_fast(gate[3]), 0.5f, 0.5f);
        ch.c  = fmaf(fs, ch.c, is * gt);
        ch.hs = os * tanh_fast(ch.c);
        ch.hx1 = __shfl_xor_sync(0xffffffffu, ch.hs, 1);
        ch.hx2 = __shfl_xor_sync(0xffffffffu, ch.hs, 2);
        ch.hx3 = __shfl_xor_sync(0xffffffffu, ch.hs, 3);
    };

    // ---- Double-buffered register prefetch: 4 steps (8 x 16B) per buffer per chain.
    ulonglong2 a0[8], a1[8], b0buf[8], b1buf[8];
#pragma unroll
    for (int j = 0; j < 8; j++) { a0[j] = xA[j];     b0buf[j] = xB[j]; }
#pragma unroll
    for (int j = 0; j < 8; j++) { a1[j] = xA[8 + j]; b1buf[j] = xB[8 + j]; }

    for (int tt = 0; tt < T_STEPS; tt += 8) {
        // steps tt..tt+3 (chains interleaved for cross-chain ILP)
#pragma unroll
        for (int s = 0; s < 4; s++) {
            STEP(cA, a0[2 * s], a0[2 * s + 1]);
            STEP(cB, b0buf[2 * s], b0buf[2 * s + 1]);
        }
        {   // refill buffer 0 with steps tt+8..tt+11 (clamped; tail loads unused)
            const int t0 = (tt + 8 < T_STEPS) ? (tt + 8) : (T_STEPS - 4);
            const ulonglong2* pA = xA + 2 * t0;
            const ulonglong2* pB = xB + 2 * t0;
#pragma unroll
            for (int j = 0; j < 8; j++) { a0[j] = pA[j]; b0buf[j] = pB[j]; }
        }
        // steps tt+4..tt+7
#pragma unroll
        for (int s = 0; s < 4; s++) {
            STEP(cA, a1[2 * s], a1[2 * s + 1]);
            STEP(cB, b1buf[2 * s], b1buf[2 * s + 1]);
        }
        {   // refill buffer 1 with steps tt+12..tt+15 (clamped)
            const int t0 = (tt + 12 < T_STEPS) ? (tt + 12) : (T_STEPS - 4);
            const ulonglong2* pA = xA + 2 * t0;
            const ulonglong2* pB = xB + 2 * t0;
#pragma unroll
            for (int j = 0; j < 8; j++) { a1[j] = pA[j]; b1buf[j] = pB[j]; }
        }
    }

    // ---- final FC: out[b] = sum_k h_k * fcw[k] + fcb ----
    const float w = fcw[k];
    float v0 = cA.hs * w;
    v0 += __shfl_xor_sync(0xffffffffu, v0, 1);
    v0 += __shfl_xor_sync(0xffffffffu, v0, 2);
    float v1 = cB.hs * w;
    v1 += __shfl_xor_sync(0xffffffffu, v1, 1);
    v1 += __shfl_xor_sync(0xffffffffu, v1, 2);
    if (k == 0) {
        out[b0] = v0 + fcb[0];
        if (b1 != b0) out[b1] = v1 + fcb[0];
    }
}

extern "C" void kernel_launch(void* const* d_in, const int* in_sizes, int n_in,
                              void* d_out, int out_size)
{
    const float* x    = (const float*)d_in[0];
    const float* Wih  = (const float*)d_in[1];
    const float* Whh  = (const float*)d_in[2];
    const float* bih  = (const float*)d_in[3];
    const float* bhh  = (const float*)d_in[4];
    const float* fcw  = (const float*)d_in[5];
    const float* fcb  = (const float*)d_in[6];
    float* out = (float*)d_out;

    const int B = in_sizes[0] / (T_STEPS * I_DIM);   // 4096
    const int nPairs = (B + 1) / 2;                  // 2048
    const int threads = nPairs * 4;                  // 8192
    const int block = 64;
    const int grid = (threads + block - 1) / block;  // 128

    lstm_kernel<<<grid, block>>>(x, Wih, Whh, bih, bhh, fcw, fcb, out, B);
}

// round 6
// speedup vs baseline: 1.1586x; 1.1586x over previous
#include <cuda_runtime.h>

// LSTM_40948218200110: B=4096, T=1024, I=8, H=4 (PyTorch gate order) + FC[H->1].
// R5: 16 threads per batch element — one thread per (gate r, hidden unit k).
// 2048 warps (3.46/SMSP) so cross-warp scheduling fills the serial-chain stalls.
// Lane u = r*4 + k within a 16-lane group; 2 groups per warp.
//  - thread computes gate row (4r+k): x-dot (8 FMA, off critical path) + h-dot (4 FMA)
//  - act = fma(tanh(z), sA, sB): sigmoid for i/f/o (0.5 prescale folded into weights),
//    plain tanh for g — uniform instruction stream via per-lane constants.
//  - i-lanes (r==0) gather f,g,o acts via 3 parallel width-16 shuffles, update c,h;
//    other lanes execute the same ops on junk (harmless).
//  - h broadcast to all 16 lanes via 4 parallel width-16 shuffles.

#define T_STEPS 1024
#define I_DIM   8

__device__ __forceinline__ float tanh_fast(float x) {
    float y;
    asm("tanh.approx.f32 %0, %1;" : "=f"(y) : "f"(x));
    return y;
}

__global__ __launch_bounds__(128, 4) void lstm_kernel(
    const float* __restrict__ x,     // [B, T, I]
    const float* __restrict__ Wih,   // [16, 8]
    const float* __restrict__ Whh,   // [16, 4]
    const float* __restrict__ bih,   // [16]
    const float* __restrict__ bhh,   // [16]
    const float* __restrict__ fcw,   // [1, 4]
    const float* __restrict__ fcb,   // [1]
    float* __restrict__ out,         // [B, 1]
    int B)
{
    const int tid = blockIdx.x * 128 + threadIdx.x;
    const int b = tid >> 4;            // batch element (16 threads each)
    const int u = tid & 15;            // 0..15 within group
    const int k = u & 3;               // hidden unit
    const int r = u >> 2;              // gate: 0=i, 1=f, 2=g, 3=o
    if (b >= B) return;

    const int row = 4 * r + k;         // row in the [16, *] weight matrices
    const float s = (r == 2) ? 1.0f : 0.5f;   // sigmoid 0.5-prescale for i/f/o
    const float sB = (r == 2) ? 0.0f : 0.5f;  // act = fma(tanh(z'), s?, sB)

    float wx[I_DIM];
#pragma unroll
    for (int j = 0; j < I_DIM; j++) wx[j] = s * Wih[row * I_DIM + j];
    float uh[4];
#pragma unroll
    for (int j = 0; j < 4; j++) uh[j] = s * Whh[row * 4 + j];
    const float bias = s * (bih[row] + bhh[row]);
    const float sA = (r == 2) ? 1.0f : 0.5f;

    const float4* xp = reinterpret_cast<const float4*>(x + (size_t)b * T_STEPS * I_DIM);

    float h0 = 0.f, h1 = 0.f, h2 = 0.f, h3 = 0.f;  // broadcast hidden state
    float c = 0.f;                                  // valid in r==0 lanes
    float hs = 0.f;                                 // valid in r==0 lanes

    const unsigned FULL = 0xffffffffu;

    auto STEP = [&](float4 xa, float4 xb) {
        // x-projection (off the recurrent critical path): two parallel sub-chains
        float z0 = fmaf(wx[0], xa.x, fmaf(wx[1], xa.y, fmaf(wx[2], xa.z, fmaf(wx[3], xa.w, bias))));
        float z1 = fmaf(wx[4], xb.x, fmaf(wx[5], xb.y, fmaf(wx[6], xb.z, wx[7] * xb.w)));
        // recurrent dot (critical path begins at h broadcast)
        z0 = fmaf(uh[0], h0, fmaf(uh[1], h1, z0));
        z1 = fmaf(uh[2], h2, fmaf(uh[3], h3, z1));
        const float z = z0 + z1;

        const float a = fmaf(tanh_fast(z), sA, sB);   // gate activation

        // gather f, g, o activations toward the i-lane of this hidden unit
        const float fv = __shfl_sync(FULL, a, k + 4,  16);
        const float gv = __shfl_sync(FULL, a, k + 8,  16);
        const float ov = __shfl_sync(FULL, a, k + 12, 16);

        // cell/hidden update — correct in r==0 lanes (a == i-activation there)
        c  = fmaf(fv, c, a * gv);
        hs = ov * tanh_fast(c);

        // broadcast the 4 hidden values (live in lanes 0..3 of each 16-group)
        h0 = __shfl_sync(FULL, hs, 0, 16);
        h1 = __shfl_sync(FULL, hs, 1, 16);
        h2 = __shfl_sync(FULL, hs, 2, 16);
        h3 = __shfl_sync(FULL, hs, 3, 16);
    };

    // ---- Double-buffered register prefetch: 4 steps (8 float4) per buffer ----
    float4 A[8], Bb[8];
#pragma unroll
    for (int j = 0; j < 8; j++) A[j]  = xp[j];
#pragma unroll
    for (int j = 0; j < 8; j++) Bb[j] = xp[8 + j];

    for (int tt = 0; tt < T_STEPS; tt += 8) {
#pragma unroll
        for (int sI = 0; sI < 4; sI++) STEP(A[2 * sI], A[2 * sI + 1]);
        {
            const int t0 = (tt + 8 < T_STEPS) ? (tt + 8) : (T_STEPS - 4);
            const float4* p = xp + 2 * t0;
#pragma unroll
            for (int j = 0; j < 8; j++) A[j] = p[j];
        }
#pragma unroll
        for (int sI = 0; sI < 4; sI++) STEP(Bb[2 * sI], Bb[2 * sI + 1]);
        {
            const int t0 = (tt + 12 < T_STEPS) ? (tt + 12) : (T_STEPS - 4);
            const float4* p = xp + 2 * t0;
#pragma unroll
            for (int j = 0; j < 8; j++) Bb[j] = p[j];
        }
    }

    // ---- final FC: all lanes hold the broadcast h; lane u==0 writes ----
    if (u == 0) {
        out[b] = fmaf(h0, fcw[0], fmaf(h1, fcw[1], fmaf(h2, fcw[2], fmaf(h3, fcw[3], fcb[0]))));
    }
}

extern "C" void kernel_launch(void* const* d_in, const int* in_sizes, int n_in,
                              void* d_out, int out_size)
{
    const float* x    = (const float*)d_in[0];
    const float* Wih  = (const float*)d_in[1];
    const float* Whh  = (const float*)d_in[2];
    const float* bih  = (const float*)d_in[3];
    const float* bhh  = (const float*)d_in[4];
    const float* fcw  = (const float*)d_in[5];
    const float* fcb  = (const float*)d_in[6];
    float* out = (float*)d_out;

    const int B = in_sizes[0] / (T_STEPS * I_DIM);   // 4096
    const int threads = B * 16;                      // 65536
    const int block = 128;
    const int grid = (threads + block - 1) / block;  // 512

    lstm_kernel<<<grid, block>>>(x, Wih, Whh, bih, bhh, fcw, fcb, out, B);
}

// round 8
// speedup vs baseline: 1.2777x; 1.1028x over previous
#include <cuda_runtime.h>

// LSTM_40948218200110: B=4096, T=1024, I=8, H=4 (PyTorch gate order) + FC[H->1].
// R6: 8 threads per batch element. Lane u = p*4 + k (p: gate-pair, k: hidden unit).
//   p=0 -> rows k (i), 4+k (f);  p=1 -> rows 8+k (g), 12+k (o).
// All dot products use packed fma.rn.f32x2 (x arrives packed via ulonglong2 loads;
// h packed with 2 movs/step). Gate exchange: 2 shfl_xor(mask 4) gives every lane
// the full (i,f,g,o) set for its unit; c/h computed redundantly in all 8 lanes.
// h broadcast: 3 shfl_xor (masks 1,2,3). 1024 warps = 1.73/SMSP.

#define T_STEPS 1024
#define I_DIM   8

typedef unsigned long long ull;

__device__ __forceinline__ float tanh_fast(float x) {
    float y;
    asm("tanh.approx.f32 %0, %1;" : "=f"(y) : "f"(x));
    return y;
}
__device__ __forceinline__ ull ffma2(ull a, ull b, ull c) {
    ull d;
    asm("fma.rn.f32x2 %0, %1, %2, %3;" : "=l"(d) : "l"(a), "l"(b), "l"(c));
    return d;
}
__device__ __forceinline__ ull pack2(float lo, float hi) {
    ull d;
    asm("mov.b64 %0, {%1, %2};" : "=l"(d) : "f"(lo), "f"(hi));
    return d;
}
__device__ __forceinline__ float hsum2(ull v) {
    float lo, hi;
    asm("mov.b64 {%0, %1}, %2;" : "=f"(lo), "=f"(hi) : "l"(v));
    return lo + hi;
}

__global__ __launch_bounds__(128, 4) void lstm_kernel(
    const float* __restrict__ x,     // [B, T, I]
    const float* __restrict__ Wih,   // [16, 8]
    const float* __restrict__ Whh,   // [16, 4]
    const float* __restrict__ bih,   // [16]
    const float* __restrict__ bhh,   // [16]
    const float* __restrict__ fcw,   // [1, 4]
    const float* __restrict__ fcb,   // [1]
    float* __restrict__ out,         // [B, 1]
    int B)
{
    const int tid = blockIdx.x * 128 + threadIdx.x;
    const int b = tid >> 3;           // batch element (8 threads each)
    const int u = tid & 7;            // lane within octet
    const int k = u & 3;              // hidden unit
    const int p = u >> 2;             // 0: (i,f) rows, 1: (g,o) rows
    if (b >= B) return;

    // Rows owned by this thread.
    const int rowA = p ? (8 + k)  : k;        // i or g
    const int rowB = p ? (12 + k) : (4 + k);  // f or o
    // sigmoid(z) = 0.5*tanh(0.5 z)+0.5: fold 0.5 prescale into weights of sigmoid rows.
    const float sA = p ? 1.0f : 0.5f;   // rowA: g uses tanh (scale 1), i uses sigmoid
    const float actA_m = p ? 1.0f : 0.5f, actA_b = p ? 0.0f : 0.5f;

    // Packed weights (held across the whole scan).
    ull wxA[4], wxB[4], whA[2], whB[2], bA, bB;
#pragma unroll
    for (int j = 0; j < 4; j++) {
        wxA[j] = pack2(sA   * Wih[rowA * I_DIM + 2 * j], sA   * Wih[rowA * I_DIM + 2 * j + 1]);
        wxB[j] = pack2(0.5f * Wih[rowB * I_DIM + 2 * j], 0.5f * Wih[rowB * I_DIM + 2 * j + 1]);
    }
    // Recurrent weights permuted by k^m to pair with shfl_xor(h, m) results.
    whA[0] = pack2(sA   * Whh[rowA * 4 + (k ^ 0)], sA   * Whh[rowA * 4 + (k ^ 1)]);
    whA[1] = pack2(sA   * Whh[rowA * 4 + (k ^ 2)], sA   * Whh[rowA * 4 + (k ^ 3)]);
    whB[0] = pack2(0.5f * Whh[rowB * 4 + (k ^ 0)], 0.5f * Whh[rowB * 4 + (k ^ 1)]);
    whB[1] = pack2(0.5f * Whh[rowB * 4 + (k ^ 2)], 0.5f * Whh[rowB * 4 + (k ^ 3)]);
    bA = pack2(sA   * (bih[rowA] + bhh[rowA]), 0.0f);
    bB = pack2(0.5f * (bih[rowB] + bhh[rowB]), 0.0f);

    const ulonglong2* xp = reinterpret_cast<const ulonglong2*>(x + (size_t)b * T_STEPS * I_DIM);

    float hs = 0.f, hx1 = 0.f, hx2 = 0.f, hx3 = 0.f;  // h_k, h_{k^1}, h_{k^2}, h_{k^3}
    float c = 0.f;
    const unsigned FULL = 0xffffffffu;

    // One step. lo = (x0,x1 | x2,x3), hi = (x4,x5 | x6,x7) packed.
    auto STEP = [&](ulonglong2 lo, ulonglong2 hi) {
        const ull h01 = pack2(hs,  hx1);
        const ull h23 = pack2(hx2, hx3);

        ull accA = ffma2(wxA[0], lo.x, bA);
        accA = ffma2(wxA[1], lo.y, accA);
        accA = ffma2(wxA[2], hi.x, accA);
        accA = ffma2(wxA[3], hi.y, accA);
        accA = ffma2(whA[0], h01, accA);
        accA = ffma2(whA[1], h23, accA);
        const float za = hsum2(accA);

        ull accB = ffma2(wxB[0], lo.x, bB);
        accB = ffma2(wxB[1], lo.y, accB);
        accB = ffma2(wxB[2], hi.x, accB);
        accB = ffma2(wxB[3], hi.y, accB);
        accB = ffma2(whB[0], h01, accB);
        accB = ffma2(whB[1], h23, accB);
        const float zb = hsum2(accB);

        // aa: p=0 -> sigmoid(i), p=1 -> tanh(g). ab: sigmoid (f or o).
        const float aa = fmaf(tanh_fast(za), actA_m, actA_b);
        const float ab = fmaf(tanh_fast(zb), 0.5f, 0.5f);

        // exchange: partner octet-half has the other gate pair
        const float e1 = __shfl_xor_sync(FULL, aa, 4);  // p0 gets g, p1 gets i
        const float e2 = __shfl_xor_sync(FULL, ab, 4);  // p0 gets o, p1 gets f

        const float fgate = p ? e2 : ab;
        const float ogate = p ? ab : e2;
        c  = fmaf(fgate, c, aa * e1);     // i*g == aa*e1 in both halves
        hs = ogate * tanh_fast(c);

        // broadcast h within the k-nibble (both halves hold correct hs)
        hx1 = __shfl_xor_sync(FULL, hs, 1);
        hx2 = __shfl_xor_sync(FULL, hs, 2);
        hx3 = __shfl_xor_sync(FULL, hs, 3);
    };

    // ---- Double-buffered register prefetch: 4 steps (8 ulonglong2) per buffer ----
    ulonglong2 A[8], Bb[8];
#pragma unroll
    for (int j = 0; j < 8; j++) A[j]  = xp[j];
#pragma unroll
    for (int j = 0; j < 8; j++) Bb[j] = xp[8 + j];

    for (int tt = 0; tt < T_STEPS; tt += 8) {
#pragma unroll
        for (int s = 0; s < 4; s++) STEP(A[2 * s], A[2 * s + 1]);
        {
            const int t0 = (tt + 8 < T_STEPS) ? (tt + 8) : (T_STEPS - 4);
            const ulonglong2* pp = xp + 2 * t0;
#pragma unroll
            for (int j = 0; j < 8; j++) A[j] = pp[j];
        }
#pragma unroll
        for (int s = 0; s < 4; s++) STEP(Bb[2 * s], Bb[2 * s + 1]);
        {
            const int t0 = (tt + 12 < T_STEPS) ? (tt + 12) : (T_STEPS - 4);
            const ulonglong2* pp = xp + 2 * t0;
#pragma unroll
            for (int j = 0; j < 8; j++) Bb[j] = pp[j];
        }
    }

    // ---- final FC: lane u==0 (k=0) holds h0=hs, h1=hx1, h2=hx2, h3=hx3 ----
    if (u == 0) {
        out[b] = fmaf(hs, fcw[0], fmaf(hx1, fcw[1], fmaf(hx2, fcw[2], fmaf(hx3, fcw[3], fcb[0]))));
    }
}

extern "C" void kernel_launch(void* const* d_in, const int* in_sizes, int n_in,
                              void* d_out, int out_size)
{
    const float* x    = (const float*)d_in[0];
    const float* Wih  = (const float*)d_in[1];
    const float* Whh  = (const float*)d_in[2];
    const float* bih  = (const float*)d_in[3];
    const float* bhh  = (const float*)d_in[4];
    const float* fcw  = (const float*)d_in[5];
    const float* fcb  = (const float*)d_in[6];
    float* out = (float*)d_out;

    const int B = in_sizes[0] / (T_STEPS * I_DIM);   // 4096
    const int threads = B * 8;                       // 32768
    const int block = 128;
    const int grid = (threads + block - 1) / block;  // 256

    lstm_kernel<<<grid, block>>>(x, Wih, Whh, bih, bhh, fcw, fcb, out, B);
}

// round 9
// speedup vs baseline: 1.6039x; 1.2553x over previous
#include <cuda_runtime.h>

// LSTM_40948218200110: B=4096, T=1024, I=8, H=4 (PyTorch gate order) + FC[H->1].
// R7: 16 threads per batch element (one per gate-row), packed fma.rn.f32x2 dot
// products, and x staged through shared memory (one coalesced 16B LDG per
// thread per 8-step chunk; per-step x via broadcast LDS.128).
// 2048 warps (3.46/SMSP) for cross-warp stall filling.
// Lane u = r*4 + k (r: gate 0=i,1=f,2=g,3=o ; k: hidden unit).
// Exchange: 3 parallel width-16 gather shfl (f,g,o to every lane) -> c/h update
// (valid in r==0 lanes, bounded junk elsewhere) -> 4 parallel broadcast shfl.

#define T_STEPS 1024
#define I_DIM   8
#define EPB     16            // elements per block
#define BLOCK   256           // threads per block
#define CH_STEPS 8            // timesteps per smem chunk
#define NCHUNK  (T_STEPS / CH_STEPS)   // 128
#define STRIDE4 17            // float4 stride per element in smem (pad 16->17)

typedef unsigned long long ull;

__device__ __forceinline__ float tanh_fast(float x) {
    float y;
    asm("tanh.approx.f32 %0, %1;" : "=f"(y) : "f"(x));
    return y;
}
__device__ __forceinline__ ull ffma2(ull a, ull b, ull c) {
    ull d;
    asm("fma.rn.f32x2 %0, %1, %2, %3;" : "=l"(d) : "l"(a), "l"(b), "l"(c));
    return d;
}
__device__ __forceinline__ ull pack2(float lo, float hi) {
    ull d;
    asm("mov.b64 %0, {%1, %2};" : "=l"(d) : "f"(lo), "f"(hi));
    return d;
}
__device__ __forceinline__ float hsum2(ull v) {
    float lo, hi;
    asm("mov.b64 {%0, %1}, %2;" : "=f"(lo), "=f"(hi) : "l"(v));
    return lo + hi;
}

__global__ __launch_bounds__(BLOCK, 2) void lstm_kernel(
    const float* __restrict__ x,     // [B, T, I]
    const float* __restrict__ Wih,   // [16, 8]
    const float* __restrict__ Whh,   // [16, 4]
    const float* __restrict__ bih,   // [16]
    const float* __restrict__ bhh,   // [16]
    const float* __restrict__ fcw,   // [1, 4]
    const float* __restrict__ fcb,   // [1]
    float* __restrict__ out,         // [B, 1]
    int B)
{
    __shared__ float4 sm[2][EPB * STRIDE4];

    const int t  = threadIdx.x;
    const int e  = t >> 4;            // local element 0..15
    const int u  = t & 15;            // lane within 16-group
    const int k  = u & 3;             // hidden unit
    const int r  = u >> 2;            // gate: 0=i,1=f,2=g,3=o
    int b = blockIdx.x * EPB + e;     // global batch element
    if (b >= B) b = B - 1;            // duplicate-compute clamp (benign rewrite)

    const int row = r * 4 + k;
    // sigmoid(z)=0.5*tanh(0.5z)+0.5 -> fold 0.5 into weights for i/f/o rows.
    const float s    = (r == 2) ? 1.0f : 0.5f;
    const float actM = (r == 2) ? 1.0f : 0.5f;
    const float actB = (r == 2) ? 0.0f : 0.5f;

    ull wx[4], wh[2], bia;
#pragma unroll
    for (int j = 0; j < 4; j++)
        wx[j] = pack2(s * Wih[row * I_DIM + 2 * j], s * Wih[row * I_DIM + 2 * j + 1]);
    wh[0] = pack2(s * Whh[row * 4 + 0], s * Whh[row * 4 + 1]);
    wh[1] = pack2(s * Whh[row * 4 + 2], s * Whh[row * 4 + 3]);
    bia = pack2(s * (bih[row] + bhh[row]), 0.0f);

    // Loader mapping: thread loads quad q of its own element's chunk.
    const int q = u;                                          // 0..15
    const float4* xf4 = reinterpret_cast<const float4*>(x + (size_t)b * T_STEPS * I_DIM);

    float h0 = 0.f, h1 = 0.f, h2 = 0.f, h3 = 0.f;
    float c = 0.f, hs = 0.f;
    const unsigned FULL = 0xffffffffu;

    // Prologue: stage chunk 0.
    sm[0][e * STRIDE4 + q] = xf4[q];
    __syncthreads();

    for (int ck = 0; ck < NCHUNK; ck++) {
        float4 pf;
        const bool more = (ck + 1 < NCHUNK);
        if (more) pf = xf4[(ck + 1) * EPB + q];      // prefetch next chunk (LDG in flight)

        const float4* buf = sm[ck & 1];
        const ulonglong2* xe = reinterpret_cast<const ulonglong2*>(buf + e * STRIDE4);

#pragma unroll
        for (int sI = 0; sI < CH_STEPS; sI++) {
            const ulonglong2 xlo = xe[2 * sI];       // x0,x1 | x2,x3 (packed pairs)
            const ulonglong2 xhi = xe[2 * sI + 1];   // x4,x5 | x6,x7

            const ull h01 = pack2(h0, h1);
            const ull h23 = pack2(h2, h3);

            ull acc = ffma2(wx[0], xlo.x, bia);
            acc = ffma2(wx[1], xlo.y, acc);
            acc = ffma2(wx[2], xhi.x, acc);
            acc = ffma2(wx[3], xhi.y, acc);
            acc = ffma2(wh[0], h01, acc);            // recurrent (critical path)
            acc = ffma2(wh[1], h23, acc);
            const float z = hsum2(acc);

            const float a = fmaf(tanh_fast(z), actM, actB);   // gate activation

            // gather f, g, o activations of unit k (3 parallel width-16 shuffles)
            const float fv = __shfl_sync(FULL, a, k + 4,  16);
            const float gv = __shfl_sync(FULL, a, k + 8,  16);
            const float ov = __shfl_sync(FULL, a, k + 12, 16);

            // c/h update — exact in r==0 lanes (a == i_k there); bounded junk elsewhere
            c  = fmaf(fv, c, a * gv);
            hs = ov * tanh_fast(c);

            // broadcast the 4 hidden values from the r==0 lanes (parallel)
            h0 = __shfl_sync(FULL, hs, 0, 16);
            h1 = __shfl_sync(FULL, hs, 1, 16);
            h2 = __shfl_sync(FULL, hs, 2, 16);
            h3 = __shfl_sync(FULL, hs, 3, 16);
        }

        if (more) sm[(ck + 1) & 1][e * STRIDE4 + q] = pf;
        __syncthreads();
    }

    // ---- final FC ----
    if (u == 0) {
        out[b] = fmaf(h0, fcw[0], fmaf(h1, fcw[1], fmaf(h2, fcw[2], fmaf(h3, fcw[3], fcb[0]))));
    }
}

extern "C" void kernel_launch(void* const* d_in, const int* in_sizes, int n_in,
                              void* d_out, int out_size)
{
    const float* x    = (const float*)d_in[0];
    const float* Wih  = (const float*)d_in[1];
    const float* Whh  = (const float*)d_in[2];
    const float* bih  = (const float*)d_in[3];
    const float* bhh  = (const float*)d_in[4];
    const float* fcw  = (const float*)d_in[5];
    const float* fcb  = (const float*)d_in[6];
    float* out = (float*)d_out;

    const int B = in_sizes[0] / (T_STEPS * I_DIM);   // 4096
    const int grid = (B + EPB - 1) / EPB;            // 256 blocks of 8 warps

    lstm_kernel<<<grid, BLOCK>>>(x, Wih, Whh, bih, bhh, fcw, fcb, out, B);
}